// round 9
// baseline (speedup 1.0000x reference)
#include <cuda_runtime.h>
#include <cstdint>

#define WINDOW   512
#define PREFIX   16
#define SEQ      4096
#define NH       16
#define BATCH    2
#define DM       1024
#define HD       64

#define NX  ((size_t)BATCH * SEQ * DM)
#define NW1 ((size_t)3 * DM * DM)
#define NW2 ((size_t)DM * DM)

// Scratch (device globals; allocation APIs are forbidden).
__device__ float g_q [(size_t)BATCH * NH * SEQ * HD];  // tf32, pre-scaled 1/8, [bh][s][d]
__device__ float g_k [(size_t)BATCH * NH * SEQ * HD];  // tf32, [bh][s][d]
__device__ float g_vt[(size_t)BATCH * NH * HD * SEQ];  // tf32, TRANSPOSED [bh][d][s]
__device__ float g_o [(size_t)BATCH * SEQ * DM];       // tf32 [b][s][h*64+d]
__device__ float g_x [NX];                             // tf32 copy of x
__device__ float g_w1[NW1];                            // tf32 copy of w_qkv
__device__ float g_w2[NW2];                            // tf32 copy of w_out

// ---------------------------------------------------------------------------
__device__ __forceinline__ void cp_async16(unsigned smem_dst, const void* gsrc) {
    asm volatile("cp.async.cg.shared.global [%0], [%1], 16;\n" :: "r"(smem_dst), "l"(gsrc));
}
__device__ __forceinline__ void cp_commit() { asm volatile("cp.async.commit_group;\n"); }
template<int N>
__device__ __forceinline__ void cp_wait() {
    asm volatile("cp.async.wait_group %0;\n" :: "n"(N));
}

__device__ __forceinline__ unsigned f2tf32(float f) {
    unsigned r;
    asm("cvt.rna.tf32.f32 %0, %1;" : "=r"(r) : "f"(f));
    return r;
}
__device__ __forceinline__ float rtf(float f) { return __uint_as_float(f2tf32(f)); }

__device__ __forceinline__ void mma_tf32(float* c, const unsigned* a, const unsigned* b) {
    asm volatile(
        "mma.sync.aligned.m16n8k8.row.col.f32.tf32.tf32.f32 "
        "{%0,%1,%2,%3}, {%4,%5,%6,%7}, {%8,%9}, {%0,%1,%2,%3};\n"
        : "+f"(c[0]), "+f"(c[1]), "+f"(c[2]), "+f"(c[3])
        : "r"(a[0]), "r"(a[1]), "r"(a[2]), "r"(a[3]), "r"(b[0]), "r"(b[1]));
}

__device__ __forceinline__ void ldsm4(unsigned& r0, unsigned& r1, unsigned& r2, unsigned& r3,
                                      unsigned addr) {
    asm volatile("ldmatrix.sync.aligned.m8n8.x4.shared.b16 {%0,%1,%2,%3}, [%4];"
                 : "=r"(r0), "=r"(r1), "=r"(r2), "=r"(r3) : "r"(addr));
}

// ---------------------------------------------------------------------------
// Prep: tf32-round x, w_qkv, w_out into scratch.
// ---------------------------------------------------------------------------
__global__ __launch_bounds__(256)
void prep_tf32(const float* __restrict__ x,
               const float* __restrict__ wq,
               const float* __restrict__ wo)
{
    size_t i = (size_t)blockIdx.x * 256 + threadIdx.x;
    const size_t nx = NX / 4, nw1 = NW1 / 4;
    const float4* src;
    float4* dst;
    size_t j;
    if (i < nx)            { src = (const float4*)x;  dst = (float4*)g_x;  j = i; }
    else if (i < nx + nw1) { src = (const float4*)wq; dst = (float4*)g_w1; j = i - nx; }
    else                   { src = (const float4*)wo; dst = (float4*)g_w2; j = i - nx - nw1; }
    float4 v = src[j];
    v.x = rtf(v.x); v.y = rtf(v.y); v.z = rtf(v.z); v.w = rtf(v.w);
    dst[j] = v;
}

// ---------------------------------------------------------------------------
// TF32 tensor-core GEMM (NT): 4-stage cp.async pipeline, ldmatrix operands.
// Block 128x128, 8 warps (2x4), warp tile 64x32, k-tiles of 16.
// ---------------------------------------------------------------------------
#define KT     16
#define KP2    20
#define NSTG   4
#define NTILE  (1024 / KT)                       // 64
#define GEMM_SMEM (NSTG * 2 * 128 * KP2 * 4)     // 81920 bytes

template<bool QKV>
__global__ __launch_bounds__(256, 2)
void gemm_tc(float* __restrict__ Cout)
{
    extern __shared__ float smem[];

    const float* A = QKV ? g_x  : g_o;
    const float* B = QKV ? g_w1 : g_w2;

    const int tid  = threadIdx.x;
    const int lane = tid & 31;
    const int wid  = tid >> 5;
    const int wm   = wid >> 2;
    const int wn   = wid & 3;
    const int m0   = blockIdx.y << 7;
    const int n0   = blockIdx.x << 7;
    const int g    = lane >> 2;
    const int t    = lane & 3;
    const int r8   = lane & 7;
    const int sel  = lane >> 3;

    float acc[4][4][4];
    #pragma unroll
    for (int i = 0; i < 4; ++i)
        #pragma unroll
        for (int j = 0; j < 4; ++j)
            #pragma unroll
            for (int r = 0; r < 4; ++r) acc[i][j][r] = 0.0f;

    const unsigned stg = 128 * KP2 * 4;          // bytes per stage per matrix
    const unsigned sA = (unsigned)__cvta_generic_to_shared(smem);
    const unsigned sB = sA + NSTG * stg;

    // ldmatrix per-lane base addresses (stage-0 byte offsets)
    const unsigned aLd = sA + (unsigned)(((wm * 64 + ((sel & 1) << 3) + r8) * KP2
                                          + ((sel >> 1) << 2)) << 2);
    const unsigned bLd = sB + (unsigned)(((wn * 32 + ((sel >> 1) << 3) + r8) * KP2
                                          + ((sel & 1) << 2)) << 2);

    // staging: 512 float4 per matrix per k-tile -> 2 per thread per matrix
    #define GSTAGE(k0, s)                                                        \
        do {                                                                     \
            _Pragma("unroll")                                                    \
            for (int it2 = 0; it2 < 2; ++it2) {                                  \
                int idx = tid + (it2 << 8);                                      \
                int row = idx >> 2;                                              \
                int c4  = (idx & 3) << 2;                                        \
                unsigned off = (unsigned)(row * KP2 + c4) * 4 + (unsigned)(s) * stg; \
                cp_async16(sA + off, A + (size_t)(m0 + row) * 1024 + (k0) + c4); \
                cp_async16(sB + off, B + (size_t)(n0 + row) * 1024 + (k0) + c4); \
            }                                                                    \
            cp_commit();                                                         \
        } while (0)

    GSTAGE(0 * KT, 0);
    GSTAGE(1 * KT, 1);
    GSTAGE(2 * KT, 2);

    for (int kt = 0; kt < NTILE; ++kt) {
        if (kt < NTILE - 2)       cp_wait<2>();
        else if (kt == NTILE - 2) cp_wait<1>();
        else                      cp_wait<0>();
        __syncthreads();

        const unsigned boff = (unsigned)(kt & 3) * stg;
        #pragma unroll
        for (int kq = 0; kq < 2; ++kq) {
            unsigned af[4][4];
            #pragma unroll
            for (int im = 0; im < 4; ++im)
                ldsm4(af[im][0], af[im][1], af[im][2], af[im][3],
                      aLd + boff + (unsigned)(im * 16 * KP2 * 4) + (unsigned)(kq * 32));
            #pragma unroll
            for (int p = 0; p < 2; ++p) {
                unsigned b0[2], b1[2];
                ldsm4(b0[0], b0[1], b1[0], b1[1],
                      bLd + boff + (unsigned)(p * 16 * KP2 * 4) + (unsigned)(kq * 32));
                #pragma unroll
                for (int im = 0; im < 4; ++im) {
                    mma_tf32(acc[im][2 * p],     af[im], b0);
                    mma_tf32(acc[im][2 * p + 1], af[im], b1);
                }
            }
        }

        if (kt + 3 < NTILE) GSTAGE((kt + 3) * KT, (kt + 3) & 3);
    }

    #pragma unroll
    for (int im = 0; im < 4; ++im) {
        #pragma unroll
        for (int jn = 0; jn < 4; ++jn) {
            int row = m0 + wm * 64 + im * 16 + g;
            int col = n0 + wn * 32 + jn * 8 + (t << 1);
            float2 v0 = make_float2(acc[im][jn][0], acc[im][jn][1]);
            float2 v1 = make_float2(acc[im][jn][2], acc[im][jn][3]);
            if (QKV) {
                int part = col >> 10;            // 0:q 1:k 2:v
                float sc = (part == 0) ? 0.125f : 1.0f;
                v0.x = rtf(v0.x * sc); v0.y = rtf(v0.y * sc);
                v1.x = rtf(v1.x * sc); v1.y = rtf(v1.y * sc);
                int nn = col & 1023;
                int h  = nn >> 6;
                int d  = nn & 63;
                int bb = row >> 12, s = row & 4095;
                if (part == 2) {
                    float* dst = g_vt + ((size_t)(bb * NH + h) * HD + d) * SEQ + s;
                    dst[0]       = v0.x;
                    dst[SEQ]     = v0.y;
                    dst[8]       = v1.x;
                    dst[SEQ + 8] = v1.y;
                } else {
                    float* dst = (part == 0) ? g_q : g_k;
                    size_t base = (((size_t)(bb * NH + h)) * SEQ) * HD + d;
                    *(float2*)(dst + base + (size_t)s * HD)       = v0;
                    *(float2*)(dst + base + (size_t)(s + 8) * HD) = v1;
                }
            } else {
                *(float2*)(Cout + (size_t)row * DM + col)       = v0;
                *(float2*)(Cout + (size_t)(row + 8) * DM + col) = v1;
            }
        }
    }
    #undef GSTAGE
}

// ---------------------------------------------------------------------------
// Tensor-core flash attention: Q in registers, cp.async double-buffered K/V^T,
// ldmatrix operands, per-warp fully-masked-tile skipping.
// Block = 128 queries; 8 warps; warp w owns rows [t0+16w, t0+16w+16).
// ---------------------------------------------------------------------------
#define ST 68
#define SM_P (4 * 64 * ST)
#define SM_TOT ((SM_P + 128 * ST) * 4)   // 104448 bytes

__global__ __launch_bounds__(256, 2)
void attn_tc()
{
    extern __shared__ float sm[];
    float* Ps = sm + SM_P;

    const int tid  = threadIdx.x;
    const int lane = tid & 31;
    const int w    = tid >> 5;
    const int g    = lane >> 2;
    const int t    = lane & 3;
    const int r8   = lane & 7;
    const int sel  = lane >> 3;
    const int bh   = blockIdx.y;
    const int t0   = blockIdx.x << 7;

    const float* Kg  = g_k  + (size_t)bh * SEQ * HD;
    const float* Vtg = g_vt + (size_t)bh * HD * SEQ;

    const unsigned sbase = (unsigned)__cvta_generic_to_shared(sm);
    const unsigned kvstg = 64 * ST * 4;

    const unsigned kLd = sbase + (unsigned)(((((sel >> 1) << 3) + r8) * ST
                                             + ((sel & 1) << 2)) << 2);
    const unsigned vLd = kLd + 2 * kvstg;
    const unsigned pLd = sbase + (unsigned)SM_P * 4
                       + (unsigned)(((w * 16 + ((sel & 1) << 3) + r8) * ST
                                     + ((sel >> 1) << 2)) << 2);

    const int rmin = t0 + w * 16;
    const int r0 = rmin + g;
    const int r1 = r0 + 8;
    unsigned qa[8][4];
    {
        const float* q0 = g_q + (size_t)bh * SEQ * HD + (size_t)r0 * HD;
        #pragma unroll
        for (int kk = 0; kk < 8; ++kk) {
            qa[kk][0] = __float_as_uint(q0[kk * 8 + t]);
            qa[kk][1] = __float_as_uint(q0[512 + kk * 8 + t]);
            qa[kk][2] = __float_as_uint(q0[kk * 8 + t + 4]);
            qa[kk][3] = __float_as_uint(q0[512 + kk * 8 + t + 4]);
        }
    }

    #define ASTAGE(kbase, s)                                                     \
        do {                                                                     \
            _Pragma("unroll")                                                    \
            for (int it2 = 0; it2 < 4; ++it2) {                                  \
                int idx = tid + (it2 << 8);                                      \
                int row = idx >> 4;                                              \
                int c4  = (idx & 15) << 2;                                       \
                unsigned off = (unsigned)(row * ST + c4) * 4 + (s) * kvstg;      \
                cp_async16(sbase + off,             Kg  + (size_t)((kbase) + row) * 64 + c4); \
                cp_async16(sbase + off + 2 * kvstg, Vtg + (size_t)row * SEQ + (kbase) + c4);  \
            }                                                                    \
            cp_commit();                                                         \
        } while (0)

    float oa[8][4];
    #pragma unroll
    for (int j = 0; j < 8; ++j)
        #pragma unroll
        for (int r = 0; r < 4; ++r) oa[j][r] = 0.0f;
    float m0 = -1e30f, m1 = -1e30f, l0 = 0.0f, l1 = 0.0f;

    int lo = t0 - (WINDOW - 1); if (lo < 0) lo = 0;
    const int lo_tile = lo >> 6;
    const int hi_tile = (t0 + 127) >> 6;
    const int extra   = (lo_tile > 0) ? 1 : 0;
    const int ntiles  = hi_tile - lo_tile + 1 + extra;

    const int prow = (w * 16 + g) * ST;

    #define KBASE(i) ((extra ? (((i) == 0) ? 0 : (lo_tile + (i) - 1)) : (lo_tile + (i))) << 6)

    ASTAGE(KBASE(0), 0);

    int buf = 0;
    for (int it = 0; it < ntiles; ++it) {
        const int kbase = KBASE(it);
        cp_wait<0>();
        __syncthreads();
        if (it + 1 < ntiles) ASTAGE(KBASE(it + 1), buf ^ 1);

        // Per-warp skip: tile contributes nothing to this warp's rows.
        // (kbase != 0 guarantees no prefix keys inside: kbase >= 64 > 16.)
        const bool skip = (kbase > rmin + 15) ||
                          ((kbase != 0) && (kbase + 63 < rmin - (WINDOW - 1)));
        if (!skip) {
            const unsigned boff = (unsigned)buf * kvstg;

            float sc[8][4];
            #pragma unroll
            for (int j = 0; j < 8; ++j)
                #pragma unroll
                for (int r = 0; r < 4; ++r) sc[j][r] = 0.0f;

            #pragma unroll
            for (int kk = 0; kk < 8; ++kk) {
                #pragma unroll
                for (int p = 0; p < 4; ++p) {
                    unsigned b0[2], b1[2];
                    ldsm4(b0[0], b0[1], b1[0], b1[1],
                          kLd + boff + (unsigned)(p * 16 * ST * 4) + (unsigned)(kk * 32));
                    mma_tf32(sc[2 * p],     qa[kk], b0);
                    mma_tf32(sc[2 * p + 1], qa[kk], b1);
                }
            }

            const bool full = (kbase + 63 <= rmin) && ((rmin + 15 - kbase) < WINDOW);
            if (!full) {
                #pragma unroll
                for (int j = 0; j < 8; ++j) {
                    int kc0 = kbase + j * 8 + (t << 1);
                    int kc1 = kc0 + 1;
                    bool a00 = (kc0 <= r0) && ((kc0 < PREFIX) || ((r0 - kc0) < WINDOW));
                    bool a01 = (kc1 <= r0) && ((kc1 < PREFIX) || ((r0 - kc1) < WINDOW));
                    bool a10 = (kc0 <= r1) && ((kc0 < PREFIX) || ((r1 - kc0) < WINDOW));
                    bool a11 = (kc1 <= r1) && ((kc1 < PREFIX) || ((r1 - kc1) < WINDOW));
                    if (!a00) sc[j][0] = -1e30f;
                    if (!a01) sc[j][1] = -1e30f;
                    if (!a10) sc[j][2] = -1e30f;
                    if (!a11) sc[j][3] = -1e30f;
                }
            }
            float rmax0 = -1e30f, rmax1 = -1e30f;
            #pragma unroll
            for (int j = 0; j < 8; ++j) {
                rmax0 = fmaxf(rmax0, fmaxf(sc[j][0], sc[j][1]));
                rmax1 = fmaxf(rmax1, fmaxf(sc[j][2], sc[j][3]));
            }
            rmax0 = fmaxf(rmax0, __shfl_xor_sync(0xffffffffu, rmax0, 1));
            rmax0 = fmaxf(rmax0, __shfl_xor_sync(0xffffffffu, rmax0, 2));
            rmax1 = fmaxf(rmax1, __shfl_xor_sync(0xffffffffu, rmax1, 1));
            rmax1 = fmaxf(rmax1, __shfl_xor_sync(0xffffffffu, rmax1, 2));

            float mn0 = fmaxf(fmaxf(m0, rmax0), -1e28f);
            float mn1 = fmaxf(fmaxf(m1, rmax1), -1e28f);
            float esc0 = __expf(m0 - mn0);
            float esc1 = __expf(m1 - mn1);

            float rs0 = 0.0f, rs1 = 0.0f;
            #pragma unroll
            for (int j = 0; j < 8; ++j) {
                float p0 = __expf(sc[j][0] - mn0);
                float p1 = __expf(sc[j][1] - mn0);
                float p2 = __expf(sc[j][2] - mn1);
                float p3 = __expf(sc[j][3] - mn1);
                rs0 += p0 + p1;
                rs1 += p2 + p3;
                int col = j * 8 + (t << 1);
                *(float2*)&Ps[prow + col]          = make_float2(rtf(p0), rtf(p1));
                *(float2*)&Ps[prow + 8 * ST + col] = make_float2(rtf(p2), rtf(p3));
            }
            rs0 += __shfl_xor_sync(0xffffffffu, rs0, 1);
            rs0 += __shfl_xor_sync(0xffffffffu, rs0, 2);
            rs1 += __shfl_xor_sync(0xffffffffu, rs1, 1);
            rs1 += __shfl_xor_sync(0xffffffffu, rs1, 2);

            l0 = l0 * esc0 + rs0;
            l1 = l1 * esc1 + rs1;
            m0 = mn0;
            m1 = mn1;
            #pragma unroll
            for (int j = 0; j < 8; ++j) {
                oa[j][0] *= esc0; oa[j][1] *= esc0;
                oa[j][2] *= esc1; oa[j][3] *= esc1;
            }
            __syncwarp();

            #pragma unroll
            for (int kk = 0; kk < 8; ++kk) {
                unsigned pa[4];
                ldsm4(pa[0], pa[1], pa[2], pa[3], pLd + (unsigned)(kk * 32));
                #pragma unroll
                for (int p = 0; p < 4; ++p) {
                    unsigned b0[2], b1[2];
                    ldsm4(b0[0], b0[1], b1[0], b1[1],
                          vLd + boff + (unsigned)(p * 16 * ST * 4) + (unsigned)(kk * 32));
                    mma_tf32(oa[2 * p],     pa, b0);
                    mma_tf32(oa[2 * p + 1], pa, b1);
                }
            }
        }
        buf ^= 1;
    }

    // Finalize: g_o[b][s][h*64+d], tf32-rounded for the out-proj GEMM
    const int b = bh >> 4, h = bh & 15;
    const float inv0 = 1.0f / l0;
    const float inv1 = 1.0f / l1;
    float* d0 = g_o + ((size_t)b * SEQ + r0) * DM + h * HD;
    float* d1 = g_o + ((size_t)b * SEQ + r1) * DM + h * HD;
    #pragma unroll
    for (int j = 0; j < 8; ++j) {
        int col = j * 8 + (t << 1);
        *(float2*)&d0[col] = make_float2(rtf(oa[j][0] * inv0), rtf(oa[j][1] * inv0));
        *(float2*)&d1[col] = make_float2(rtf(oa[j][2] * inv1), rtf(oa[j][3] * inv1));
    }
    #undef ASTAGE
    #undef KBASE
}

// ---------------------------------------------------------------------------
extern "C" void kernel_launch(void* const* d_in, const int* in_sizes, int n_in,
                              void* d_out, int out_size)
{
    const float* x     = (const float*)d_in[0];
    const float* w_qkv = (const float*)d_in[1];
    const float* w_out = (const float*)d_in[2];
    float* out = (float*)d_out;

    cudaFuncSetAttribute(gemm_tc<true>,  cudaFuncAttributeMaxDynamicSharedMemorySize, GEMM_SMEM);
    cudaFuncSetAttribute(gemm_tc<false>, cudaFuncAttributeMaxDynamicSharedMemorySize, GEMM_SMEM);
    cudaFuncSetAttribute(attn_tc,        cudaFuncAttributeMaxDynamicSharedMemorySize, SM_TOT);

    // 0) tf32-round all GEMM inputs once
    prep_tf32<<<(unsigned)((NX + NW1 + NW2) / 4 / 256), 256>>>(x, w_qkv, w_out);
    // 1) QKV projection -> g_q/g_k/g_vt (v transposed)
    gemm_tc<true><<<dim3(3072 / 128, 8192 / 128), 256, GEMM_SMEM>>>(nullptr);
    // 2) tensor-core flash attention -> g_o (tf32)
    attn_tc<<<dim3(SEQ / 128, BATCH * NH), 256, SM_TOT>>>();
    // 3) output projection -> d_out (f32)
    gemm_tc<false><<<dim3(1024 / 128, 8192 / 128), 256, GEMM_SMEM>>>(out);
}

// round 10
// speedup vs baseline: 1.2160x; 1.2160x over previous
#include <cuda_runtime.h>
#include <cstdint>

#define WINDOW   512
#define PREFIX   16
#define SEQ      4096
#define NH       16
#define BATCH    2
#define DM       1024
#define HD       64

#define NX  ((size_t)BATCH * SEQ * DM)
#define NW1 ((size_t)3 * DM * DM)
#define NW2 ((size_t)DM * DM)

// Scratch (device globals; allocation APIs are forbidden).
__device__ float g_q [(size_t)BATCH * NH * SEQ * HD];  // tf32, pre-scaled 1/8, [bh][s][d]
__device__ float g_k [(size_t)BATCH * NH * SEQ * HD];  // tf32, [bh][s][d]
__device__ float g_vt[(size_t)BATCH * NH * HD * SEQ];  // tf32, TRANSPOSED [bh][d][s]
__device__ float g_o [(size_t)BATCH * SEQ * DM];       // tf32 [b][s][h*64+d]
__device__ float g_x [NX];                             // tf32 copy of x
__device__ float g_w1[NW1];                            // tf32 copy of w_qkv
__device__ float g_w2[NW2];                            // tf32 copy of w_out

// ---------------------------------------------------------------------------
__device__ __forceinline__ void cp_async16(unsigned smem_dst, const void* gsrc) {
    asm volatile("cp.async.cg.shared.global [%0], [%1], 16;\n" :: "r"(smem_dst), "l"(gsrc));
}
__device__ __forceinline__ void cp_commit() { asm volatile("cp.async.commit_group;\n"); }
template<int N>
__device__ __forceinline__ void cp_wait() {
    asm volatile("cp.async.wait_group %0;\n" :: "n"(N));
}

__device__ __forceinline__ unsigned f2tf32(float f) {
    unsigned r;
    asm("cvt.rna.tf32.f32 %0, %1;" : "=r"(r) : "f"(f));
    return r;
}
__device__ __forceinline__ float rtf(float f) { return __uint_as_float(f2tf32(f)); }

__device__ __forceinline__ void mma_tf32(float* c, const unsigned* a, const unsigned* b) {
    asm volatile(
        "mma.sync.aligned.m16n8k8.row.col.f32.tf32.tf32.f32 "
        "{%0,%1,%2,%3}, {%4,%5,%6,%7}, {%8,%9}, {%0,%1,%2,%3};\n"
        : "+f"(c[0]), "+f"(c[1]), "+f"(c[2]), "+f"(c[3])
        : "r"(a[0]), "r"(a[1]), "r"(a[2]), "r"(a[3]), "r"(b[0]), "r"(b[1]));
}

__device__ __forceinline__ void ldsm4(unsigned& r0, unsigned& r1, unsigned& r2, unsigned& r3,
                                      unsigned addr) {
    asm volatile("ldmatrix.sync.aligned.m8n8.x4.shared.b16 {%0,%1,%2,%3}, [%4];"
                 : "=r"(r0), "=r"(r1), "=r"(r2), "=r"(r3) : "r"(addr));
}

// ---------------------------------------------------------------------------
// Prep: tf32-round x, w_qkv, w_out into scratch.
// ---------------------------------------------------------------------------
__global__ __launch_bounds__(256)
void prep_tf32(const float* __restrict__ x,
               const float* __restrict__ wq,
               const float* __restrict__ wo)
{
    size_t i = (size_t)blockIdx.x * 256 + threadIdx.x;
    const size_t nx = NX / 4, nw1 = NW1 / 4;
    const float4* src;
    float4* dst;
    size_t j;
    if (i < nx)            { src = (const float4*)x;  dst = (float4*)g_x;  j = i; }
    else if (i < nx + nw1) { src = (const float4*)wq; dst = (float4*)g_w1; j = i - nx; }
    else                   { src = (const float4*)wo; dst = (float4*)g_w2; j = i - nx - nw1; }
    float4 v = src[j];
    v.x = rtf(v.x); v.y = rtf(v.y); v.z = rtf(v.z); v.w = rtf(v.w);
    dst[j] = v;
}

// ---------------------------------------------------------------------------
// TF32 tensor-core GEMM (NT): 3-stage cp.async pipeline, XOR-swizzled smem
// (no padding), ldmatrix operands. Block 128x128, warp tile 64x32, KT=32.
// Swizzle: row r, 16B-chunk c -> phys chunk c ^ (r & 7). All ldmatrix lane
// rows have (row & 7) == (lane & 7), so the mask is lane-constant.
// ---------------------------------------------------------------------------
#define KT     32
#define NTILE  (1024 / KT)                  // 32
#define NSTG   3
#define TILEB  (128 * KT * 4)               // 16384 bytes per matrix per stage
#define GEMM_SMEM (NSTG * 2 * TILEB)        // 98304 bytes

template<bool QKV>
__global__ __launch_bounds__(256, 2)
void gemm_tc(float* __restrict__ Cout)
{
    extern __shared__ float smem[];

    const float* A = QKV ? g_x  : g_o;
    const float* B = QKV ? g_w1 : g_w2;

    const int tid  = threadIdx.x;
    const int lane = tid & 31;
    const int wid  = tid >> 5;
    const int wm   = wid >> 2;
    const int wn   = wid & 3;
    const int m0   = blockIdx.y << 7;
    const int n0   = blockIdx.x << 7;
    const int g    = lane >> 2;
    const int t    = lane & 3;
    const int r8   = lane & 7;
    const int sel  = lane >> 3;

    float acc[4][4][4];
    #pragma unroll
    for (int i = 0; i < 4; ++i)
        #pragma unroll
        for (int j = 0; j < 4; ++j)
            #pragma unroll
            for (int r = 0; r < 4; ++r) acc[i][j][r] = 0.0f;

    const unsigned sA = (unsigned)__cvta_generic_to_shared(smem);
    const unsigned sB = sA + NSTG * TILEB;

    // per-lane ldmatrix row bases (byte offset within a tile; 128 B per row)
    const unsigned aRow = (unsigned)((wm * 64 + ((sel & 1) << 3) + r8) * 128);
    const unsigned bRow = (unsigned)((wn * 32 + ((sel >> 1) << 3) + r8) * 128);
    const int acp = sel >> 1;   // A chunk part (k 0-3 vs 4-7)
    const int bcp = sel & 1;    // B chunk part

    // staging: 1024 16B-chunks per matrix per tile -> 4 per thread per matrix
    #define GSTAGE(k0, s)                                                        \
        do {                                                                     \
            _Pragma("unroll")                                                    \
            for (int it2 = 0; it2 < 4; ++it2) {                                  \
                int idx = tid + (it2 << 8);                                      \
                int row = idx >> 3;                                              \
                int c   = idx & 7;                                               \
                unsigned off = (unsigned)(row * 128 + (((c ^ (row & 7))) << 4))  \
                             + (unsigned)(s) * TILEB;                            \
                cp_async16(sA + off, A + (size_t)(m0 + row) * 1024 + (k0) + c * 4); \
                cp_async16(sB + off, B + (size_t)(n0 + row) * 1024 + (k0) + c * 4); \
            }                                                                    \
            cp_commit();                                                         \
        } while (0)

    GSTAGE(0 * KT, 0);
    GSTAGE(1 * KT, 1);

    for (int kt = 0; kt < NTILE; ++kt) {
        if (kt < NTILE - 1) cp_wait<1>();    // tile kt resident (issued 2 iters ago)
        else                cp_wait<0>();
        __syncthreads();
        if (kt + 2 < NTILE) GSTAGE((kt + 2) * KT, (kt + 2) % NSTG);

        const unsigned aT = sA + (unsigned)(kt % NSTG) * TILEB;
        const unsigned bT = sB + (unsigned)(kt % NSTG) * TILEB;

        #pragma unroll
        for (int kq = 0; kq < 4; ++kq) {
            const unsigned axc = (unsigned)(((2 * kq + acp) ^ r8) << 4);
            const unsigned bxc = (unsigned)(((2 * kq + bcp) ^ r8) << 4);
            unsigned af[4][4];
            #pragma unroll
            for (int im = 0; im < 4; ++im)
                ldsm4(af[im][0], af[im][1], af[im][2], af[im][3],
                      aT + aRow + (unsigned)(im * 2048) + axc);
            #pragma unroll
            for (int p = 0; p < 2; ++p) {
                unsigned b0[2], b1[2];
                ldsm4(b0[0], b0[1], b1[0], b1[1],
                      bT + bRow + (unsigned)(p * 2048) + bxc);
                #pragma unroll
                for (int im = 0; im < 4; ++im) {
                    mma_tf32(acc[im][2 * p],     af[im], b0);
                    mma_tf32(acc[im][2 * p + 1], af[im], b1);
                }
            }
        }
    }

    #pragma unroll
    for (int im = 0; im < 4; ++im) {
        #pragma unroll
        for (int jn = 0; jn < 4; ++jn) {
            int row = m0 + wm * 64 + im * 16 + g;
            int col = n0 + wn * 32 + jn * 8 + (t << 1);
            float2 v0 = make_float2(acc[im][jn][0], acc[im][jn][1]);
            float2 v1 = make_float2(acc[im][jn][2], acc[im][jn][3]);
            if (QKV) {
                int part = col >> 10;            // 0:q 1:k 2:v
                float sc = (part == 0) ? 0.125f : 1.0f;
                v0.x = rtf(v0.x * sc); v0.y = rtf(v0.y * sc);
                v1.x = rtf(v1.x * sc); v1.y = rtf(v1.y * sc);
                int nn = col & 1023;
                int h  = nn >> 6;
                int d  = nn & 63;
                int bb = row >> 12, s = row & 4095;
                if (part == 2) {
                    float* dst = g_vt + ((size_t)(bb * NH + h) * HD + d) * SEQ + s;
                    dst[0]       = v0.x;
                    dst[SEQ]     = v0.y;
                    dst[8]       = v1.x;
                    dst[SEQ + 8] = v1.y;
                } else {
                    float* dst = (part == 0) ? g_q : g_k;
                    size_t base = (((size_t)(bb * NH + h)) * SEQ) * HD + d;
                    *(float2*)(dst + base + (size_t)s * HD)       = v0;
                    *(float2*)(dst + base + (size_t)(s + 8) * HD) = v1;
                }
            } else {
                *(float2*)(Cout + (size_t)row * DM + col)       = v0;
                *(float2*)(Cout + (size_t)(row + 8) * DM + col) = v1;
            }
        }
    }
    #undef GSTAGE
}

// ---------------------------------------------------------------------------
// Tensor-core flash attention (round-8 version: no per-warp skip).
// Q in registers, cp.async double-buffered K/V^T, ldmatrix operands.
// Block = 128 queries; 8 warps; warp w owns rows [t0+16w, t0+16w+16).
// ---------------------------------------------------------------------------
#define ST 68
#define SM_P (4 * 64 * ST)
#define SM_TOT ((SM_P + 128 * ST) * 4)   // 104448 bytes

__global__ __launch_bounds__(256, 2)
void attn_tc()
{
    extern __shared__ float sm[];
    float* Ps = sm + SM_P;

    const int tid  = threadIdx.x;
    const int lane = tid & 31;
    const int w    = tid >> 5;
    const int g    = lane >> 2;
    const int t    = lane & 3;
    const int r8   = lane & 7;
    const int sel  = lane >> 3;
    const int bh   = blockIdx.y;
    const int t0   = blockIdx.x << 7;

    const float* Kg  = g_k  + (size_t)bh * SEQ * HD;
    const float* Vtg = g_vt + (size_t)bh * HD * SEQ;

    const unsigned sbase = (unsigned)__cvta_generic_to_shared(sm);
    const unsigned kvstg = 64 * ST * 4;

    const unsigned kLd = sbase + (unsigned)(((((sel >> 1) << 3) + r8) * ST
                                             + ((sel & 1) << 2)) << 2);
    const unsigned vLd = kLd + 2 * kvstg;
    const unsigned pLd = sbase + (unsigned)SM_P * 4
                       + (unsigned)(((w * 16 + ((sel & 1) << 3) + r8) * ST
                                     + ((sel >> 1) << 2)) << 2);

    const int rmin = t0 + w * 16;
    const int r0 = rmin + g;
    const int r1 = r0 + 8;
    unsigned qa[8][4];
    {
        const float* q0 = g_q + (size_t)bh * SEQ * HD + (size_t)r0 * HD;
        #pragma unroll
        for (int kk = 0; kk < 8; ++kk) {
            qa[kk][0] = __float_as_uint(q0[kk * 8 + t]);
            qa[kk][1] = __float_as_uint(q0[512 + kk * 8 + t]);
            qa[kk][2] = __float_as_uint(q0[kk * 8 + t + 4]);
            qa[kk][3] = __float_as_uint(q0[512 + kk * 8 + t + 4]);
        }
    }

    #define ASTAGE(kbase, s)                                                     \
        do {                                                                     \
            _Pragma("unroll")                                                    \
            for (int it2 = 0; it2 < 4; ++it2) {                                  \
                int idx = tid + (it2 << 8);                                      \
                int row = idx >> 4;                                              \
                int c4  = (idx & 15) << 2;                                       \
                unsigned off = (unsigned)(row * ST + c4) * 4 + (s) * kvstg;      \
                cp_async16(sbase + off,             Kg  + (size_t)((kbase) + row) * 64 + c4); \
                cp_async16(sbase + off + 2 * kvstg, Vtg + (size_t)row * SEQ + (kbase) + c4);  \
            }                                                                    \
            cp_commit();                                                         \
        } while (0)

    float oa[8][4];
    #pragma unroll
    for (int j = 0; j < 8; ++j)
        #pragma unroll
        for (int r = 0; r < 4; ++r) oa[j][r] = 0.0f;
    float m0 = -1e30f, m1 = -1e30f, l0 = 0.0f, l1 = 0.0f;

    int lo = t0 - (WINDOW - 1); if (lo < 0) lo = 0;
    const int lo_tile = lo >> 6;
    const int hi_tile = (t0 + 127) >> 6;
    const int extra   = (lo_tile > 0) ? 1 : 0;
    const int ntiles  = hi_tile - lo_tile + 1 + extra;

    const int prow = (w * 16 + g) * ST;

    #define KBASE(i) ((extra ? (((i) == 0) ? 0 : (lo_tile + (i) - 1)) : (lo_tile + (i))) << 6)

    ASTAGE(KBASE(0), 0);

    int buf = 0;
    for (int it = 0; it < ntiles; ++it) {
        const int kbase = KBASE(it);
        cp_wait<0>();
        __syncthreads();
        if (it + 1 < ntiles) ASTAGE(KBASE(it + 1), buf ^ 1);

        const unsigned boff = (unsigned)buf * kvstg;

        // S = Q K^T : 16 x 64 per warp
        float sc[8][4];
        #pragma unroll
        for (int j = 0; j < 8; ++j)
            #pragma unroll
            for (int r = 0; r < 4; ++r) sc[j][r] = 0.0f;

        #pragma unroll
        for (int kk = 0; kk < 8; ++kk) {
            #pragma unroll
            for (int p = 0; p < 4; ++p) {
                unsigned b0[2], b1[2];
                ldsm4(b0[0], b0[1], b1[0], b1[1],
                      kLd + boff + (unsigned)(p * 16 * ST * 4) + (unsigned)(kk * 32));
                mma_tf32(sc[2 * p],     qa[kk], b0);
                mma_tf32(sc[2 * p + 1], qa[kk], b1);
            }
        }

        const bool full = (kbase + 63 <= rmin) && ((rmin + 15 - kbase) < WINDOW);
        if (!full) {
            #pragma unroll
            for (int j = 0; j < 8; ++j) {
                int kc0 = kbase + j * 8 + (t << 1);
                int kc1 = kc0 + 1;
                bool a00 = (kc0 <= r0) && ((kc0 < PREFIX) || ((r0 - kc0) < WINDOW));
                bool a01 = (kc1 <= r0) && ((kc1 < PREFIX) || ((r0 - kc1) < WINDOW));
                bool a10 = (kc0 <= r1) && ((kc0 < PREFIX) || ((r1 - kc0) < WINDOW));
                bool a11 = (kc1 <= r1) && ((kc1 < PREFIX) || ((r1 - kc1) < WINDOW));
                if (!a00) sc[j][0] = -1e30f;
                if (!a01) sc[j][1] = -1e30f;
                if (!a10) sc[j][2] = -1e30f;
                if (!a11) sc[j][3] = -1e30f;
            }
        }
        float rmax0 = -1e30f, rmax1 = -1e30f;
        #pragma unroll
        for (int j = 0; j < 8; ++j) {
            rmax0 = fmaxf(rmax0, fmaxf(sc[j][0], sc[j][1]));
            rmax1 = fmaxf(rmax1, fmaxf(sc[j][2], sc[j][3]));
        }
        rmax0 = fmaxf(rmax0, __shfl_xor_sync(0xffffffffu, rmax0, 1));
        rmax0 = fmaxf(rmax0, __shfl_xor_sync(0xffffffffu, rmax0, 2));
        rmax1 = fmaxf(rmax1, __shfl_xor_sync(0xffffffffu, rmax1, 1));
        rmax1 = fmaxf(rmax1, __shfl_xor_sync(0xffffffffu, rmax1, 2));

        float mn0 = fmaxf(fmaxf(m0, rmax0), -1e28f);
        float mn1 = fmaxf(fmaxf(m1, rmax1), -1e28f);
        float esc0 = __expf(m0 - mn0);
        float esc1 = __expf(m1 - mn1);

        float rs0 = 0.0f, rs1 = 0.0f;
        #pragma unroll
        for (int j = 0; j < 8; ++j) {
            float p0 = __expf(sc[j][0] - mn0);
            float p1 = __expf(sc[j][1] - mn0);
            float p2 = __expf(sc[j][2] - mn1);
            float p3 = __expf(sc[j][3] - mn1);
            rs0 += p0 + p1;
            rs1 += p2 + p3;
            int col = j * 8 + (t << 1);
            *(float2*)&Ps[prow + col]          = make_float2(rtf(p0), rtf(p1));
            *(float2*)&Ps[prow + 8 * ST + col] = make_float2(rtf(p2), rtf(p3));
        }
        rs0 += __shfl_xor_sync(0xffffffffu, rs0, 1);
        rs0 += __shfl_xor_sync(0xffffffffu, rs0, 2);
        rs1 += __shfl_xor_sync(0xffffffffu, rs1, 1);
        rs1 += __shfl_xor_sync(0xffffffffu, rs1, 2);

        l0 = l0 * esc0 + rs0;
        l1 = l1 * esc1 + rs1;
        m0 = mn0;
        m1 = mn1;
        #pragma unroll
        for (int j = 0; j < 8; ++j) {
            oa[j][0] *= esc0; oa[j][1] *= esc0;
            oa[j][2] *= esc1; oa[j][3] *= esc1;
        }
        __syncwarp();

        #pragma unroll
        for (int kk = 0; kk < 8; ++kk) {
            unsigned pa[4];
            ldsm4(pa[0], pa[1], pa[2], pa[3], pLd + (unsigned)(kk * 32));
            #pragma unroll
            for (int p = 0; p < 4; ++p) {
                unsigned b0[2], b1[2];
                ldsm4(b0[0], b0[1], b1[0], b1[1],
                      vLd + boff + (unsigned)(p * 16 * ST * 4) + (unsigned)(kk * 32));
                mma_tf32(oa[2 * p],     pa, b0);
                mma_tf32(oa[2 * p + 1], pa, b1);
            }
        }
        buf ^= 1;
    }

    // Finalize: g_o[b][s][h*64+d], tf32-rounded for the out-proj GEMM
    const int b = bh >> 4, h = bh & 15;
    const float inv0 = 1.0f / l0;
    const float inv1 = 1.0f / l1;
    float* d0 = g_o + ((size_t)b * SEQ + r0) * DM + h * HD;
    float* d1 = g_o + ((size_t)b * SEQ + r1) * DM + h * HD;
    #pragma unroll
    for (int j = 0; j < 8; ++j) {
        int col = j * 8 + (t << 1);
        *(float2*)&d0[col] = make_float2(rtf(oa[j][0] * inv0), rtf(oa[j][1] * inv0));
        *(float2*)&d1[col] = make_float2(rtf(oa[j][2] * inv1), rtf(oa[j][3] * inv1));
    }
    #undef ASTAGE
    #undef KBASE
}

// ---------------------------------------------------------------------------
extern "C" void kernel_launch(void* const* d_in, const int* in_sizes, int n_in,
                              void* d_out, int out_size)
{
    const float* x     = (const float*)d_in[0];
    const float* w_qkv = (const float*)d_in[1];
    const float* w_out = (const float*)d_in[2];
    float* out = (float*)d_out;

    cudaFuncSetAttribute(gemm_tc<true>,  cudaFuncAttributeMaxDynamicSharedMemorySize, GEMM_SMEM);
    cudaFuncSetAttribute(gemm_tc<false>, cudaFuncAttributeMaxDynamicSharedMemorySize, GEMM_SMEM);
    cudaFuncSetAttribute(attn_tc,        cudaFuncAttributeMaxDynamicSharedMemorySize, SM_TOT);

    // 0) tf32-round all GEMM inputs once
    prep_tf32<<<(unsigned)((NX + NW1 + NW2) / 4 / 256), 256>>>(x, w_qkv, w_out);
    // 1) QKV projection -> g_q/g_k/g_vt (v transposed)
    gemm_tc<true><<<dim3(3072 / 128, 8192 / 128), 256, GEMM_SMEM>>>(nullptr);
    // 2) tensor-core flash attention -> g_o (tf32)
    attn_tc<<<dim3(SEQ / 128, BATCH * NH), 256, SM_TOT>>>();
    // 3) output projection -> d_out (f32)
    gemm_tc<false><<<dim3(1024 / 128, 8192 / 128), 256, GEMM_SMEM>>>(out);
}

// round 11
// speedup vs baseline: 2.1591x; 1.7756x over previous
#include <cuda_runtime.h>
#include <cuda_fp16.h>
#include <cstdint>

#define WINDOW   512
#define PREFIX   16
#define SEQ      4096
#define NH       16
#define BATCH    2
#define DM       1024
#define HD       64

#define NX  ((size_t)BATCH * SEQ * DM)
#define NW1 ((size_t)3 * DM * DM)
#define NW2 ((size_t)DM * DM)

// Scratch (device globals; allocation APIs are forbidden). All fp16.
__device__ __half g_q [(size_t)BATCH * NH * SEQ * HD];  // pre-scaled 1/8, [bh][s][d]
__device__ __half g_k [(size_t)BATCH * NH * SEQ * HD];  // [bh][s][d]
__device__ __half g_vt[(size_t)BATCH * NH * HD * SEQ];  // TRANSPOSED [bh][d][s]
__device__ __half g_o [(size_t)BATCH * SEQ * DM];       // [b][s][h*64+d]
__device__ __half g_x [NX];                             // fp16 copy of x
__device__ __half g_w1[NW1];                            // fp16 copy of w_qkv
__device__ __half g_w2[NW2];                            // fp16 copy of w_out

// ---------------------------------------------------------------------------
__device__ __forceinline__ void cp_async16(unsigned smem_dst, const void* gsrc) {
    asm volatile("cp.async.cg.shared.global [%0], [%1], 16;\n" :: "r"(smem_dst), "l"(gsrc));
}
__device__ __forceinline__ void cp_commit() { asm volatile("cp.async.commit_group;\n"); }
template<int N>
__device__ __forceinline__ void cp_wait() {
    asm volatile("cp.async.wait_group %0;\n" :: "n"(N));
}

__device__ __forceinline__ void mma_f16(float* c, const unsigned* a, const unsigned* b) {
    asm volatile(
        "mma.sync.aligned.m16n8k16.row.col.f32.f16.f16.f32 "
        "{%0,%1,%2,%3}, {%4,%5,%6,%7}, {%8,%9}, {%0,%1,%2,%3};\n"
        : "+f"(c[0]), "+f"(c[1]), "+f"(c[2]), "+f"(c[3])
        : "r"(a[0]), "r"(a[1]), "r"(a[2]), "r"(a[3]), "r"(b[0]), "r"(b[1]));
}

__device__ __forceinline__ void ldsm4(unsigned& r0, unsigned& r1, unsigned& r2, unsigned& r3,
                                      unsigned addr) {
    asm volatile("ldmatrix.sync.aligned.m8n8.x4.shared.b16 {%0,%1,%2,%3}, [%4];"
                 : "=r"(r0), "=r"(r1), "=r"(r2), "=r"(r3) : "r"(addr));
}

// ---------------------------------------------------------------------------
// Prep: fp16-convert x, w_qkv, w_out into scratch.
// ---------------------------------------------------------------------------
__global__ __launch_bounds__(256)
void prep_f16(const float* __restrict__ x,
              const float* __restrict__ wq,
              const float* __restrict__ wo)
{
    size_t i = (size_t)blockIdx.x * 256 + threadIdx.x;   // float4 index
    const size_t nx = NX / 4, nw1 = NW1 / 4;
    const float4* src;
    __half* dst;
    size_t j;
    if (i < nx)            { src = (const float4*)x;  dst = g_x;  j = i; }
    else if (i < nx + nw1) { src = (const float4*)wq; dst = g_w1; j = i - nx; }
    else                   { src = (const float4*)wo; dst = g_w2; j = i - nx - nw1; }
    float4 v = src[j];
    __half2 h0 = __floats2half2_rn(v.x, v.y);
    __half2 h1 = __floats2half2_rn(v.z, v.w);
    *(__half2*)(dst + 4 * j)     = h0;
    *(__half2*)(dst + 4 * j + 2) = h1;
}

// ---------------------------------------------------------------------------
// FP16 tensor-core GEMM (NT): 3-stage cp.async pipeline, XOR-swizzled smem,
// ldmatrix operands, m16n8k16. Block 128x128, warp tile 64x32, KT=64.
// Rows are 128 B (64 fp16); 16B chunk c at row r lives at phys chunk c^(r&7).
// ---------------------------------------------------------------------------
#define KT     64
#define NTILE  (1024 / KT)                  // 16
#define NSTG   3
#define TILEB  (128 * 128)                  // 16384 bytes per matrix per stage
#define GEMM_SMEM (NSTG * 2 * TILEB)        // 98304 bytes

template<bool QKV>
__global__ __launch_bounds__(256, 2)
void gemm_f16(float* __restrict__ Cout)
{
    extern __shared__ char smc[];

    const __half* A = QKV ? g_x  : g_o;
    const __half* B = QKV ? g_w1 : g_w2;

    const int tid  = threadIdx.x;
    const int lane = tid & 31;
    const int wid  = tid >> 5;
    const int wm   = wid >> 2;
    const int wn   = wid & 3;
    const int m0   = blockIdx.y << 7;
    const int n0   = blockIdx.x << 7;
    const int g    = lane >> 2;
    const int t    = lane & 3;
    const int r8   = lane & 7;
    const int sel  = lane >> 3;

    float acc[4][4][4];
    #pragma unroll
    for (int i = 0; i < 4; ++i)
        #pragma unroll
        for (int j = 0; j < 4; ++j)
            #pragma unroll
            for (int r = 0; r < 4; ++r) acc[i][j][r] = 0.0f;

    const unsigned sA = (unsigned)__cvta_generic_to_shared(smc);
    const unsigned sB = sA + NSTG * TILEB;

    // per-lane ldmatrix row bases (byte offsets within a tile)
    const unsigned aRow = (unsigned)((wm * 64 + ((sel & 1) << 3) + r8) * 128);
    const unsigned bRow = (unsigned)((wn * 32 + ((sel >> 1) << 3) + r8) * 128);
    const int ac = sel >> 1;    // A chunk half (k 0-7 vs 8-15 within k16)
    const int bc = sel & 1;     // B chunk half

    // staging: 1024 16B-chunks per matrix per tile -> 4 per thread per matrix
    #define GSTAGE(k0, s)                                                        \
        do {                                                                     \
            _Pragma("unroll")                                                    \
            for (int it2 = 0; it2 < 4; ++it2) {                                  \
                int idx = tid + (it2 << 8);                                      \
                int row = idx >> 3;                                              \
                int c   = idx & 7;                                               \
                unsigned off = (unsigned)(row * 128 + ((c ^ (row & 7)) << 4))    \
                             + (unsigned)(s) * TILEB;                            \
                cp_async16(sA + off, A + (size_t)(m0 + row) * 1024 + (k0) + c * 8); \
                cp_async16(sB + off, B + (size_t)(n0 + row) * 1024 + (k0) + c * 8); \
            }                                                                    \
            cp_commit();                                                         \
        } while (0)

    GSTAGE(0 * KT, 0);
    GSTAGE(1 * KT, 1);

    for (int kt = 0; kt < NTILE; ++kt) {
        if (kt < NTILE - 1) cp_wait<1>();
        else                cp_wait<0>();
        __syncthreads();
        if (kt + 2 < NTILE) GSTAGE((kt + 2) * KT, (kt + 2) % NSTG);

        const unsigned aT = sA + (unsigned)(kt % NSTG) * TILEB;
        const unsigned bT = sB + (unsigned)(kt % NSTG) * TILEB;

        #pragma unroll
        for (int kg = 0; kg < 4; ++kg) {          // 4 x k16 per tile
            const unsigned axc = (unsigned)(((2 * kg + ac) ^ r8) << 4);
            const unsigned bxc = (unsigned)(((2 * kg + bc) ^ r8) << 4);
            unsigned af[4][4];
            #pragma unroll
            for (int im = 0; im < 4; ++im)
                ldsm4(af[im][0], af[im][1], af[im][2], af[im][3],
                      aT + aRow + (unsigned)(im * 2048) + axc);
            #pragma unroll
            for (int p = 0; p < 2; ++p) {
                unsigned b0[2], b1[2];
                ldsm4(b0[0], b0[1], b1[0], b1[1],
                      bT + bRow + (unsigned)(p * 2048) + bxc);
                #pragma unroll
                for (int im = 0; im < 4; ++im) {
                    mma_f16(acc[im][2 * p],     af[im], b0);
                    mma_f16(acc[im][2 * p + 1], af[im], b1);
                }
            }
        }
    }

    #pragma unroll
    for (int im = 0; im < 4; ++im) {
        #pragma unroll
        for (int jn = 0; jn < 4; ++jn) {
            int row = m0 + wm * 64 + im * 16 + g;
            int col = n0 + wn * 32 + jn * 8 + (t << 1);
            if (QKV) {
                int part = col >> 10;            // 0:q 1:k 2:v
                float sc = (part == 0) ? 0.125f : 1.0f;
                __half2 h0 = __floats2half2_rn(acc[im][jn][0] * sc, acc[im][jn][1] * sc);
                __half2 h1 = __floats2half2_rn(acc[im][jn][2] * sc, acc[im][jn][3] * sc);
                int nn = col & 1023;
                int h  = nn >> 6;
                int d  = nn & 63;
                int bb = row >> 12, s = row & 4095;
                if (part == 2) {
                    __half* dst = g_vt + ((size_t)(bb * NH + h) * HD + d) * SEQ + s;
                    dst[0]       = __low2half(h0);
                    dst[SEQ]     = __high2half(h0);
                    dst[8]       = __low2half(h1);
                    dst[SEQ + 8] = __high2half(h1);
                } else {
                    __half* dst = (part == 0) ? g_q : g_k;
                    size_t base = (((size_t)(bb * NH + h)) * SEQ) * HD + d;
                    *(__half2*)(dst + base + (size_t)s * HD)       = h0;
                    *(__half2*)(dst + base + (size_t)(s + 8) * HD) = h1;
                }
            } else {
                *(float2*)(Cout + (size_t)row * DM + col) =
                    make_float2(acc[im][jn][0], acc[im][jn][1]);
                *(float2*)(Cout + (size_t)(row + 8) * DM + col) =
                    make_float2(acc[im][jn][2], acc[im][jn][3]);
            }
        }
    }
    #undef GSTAGE
}

// ---------------------------------------------------------------------------
// FP16 tensor-core flash attention: Q in registers, cp.async double-buffered
// K/V^T, ldmatrix operands, m16n8k16.
// Block = 128 queries; 8 warps; warp w owns rows [t0+16w, t0+16w+16).
// Smem: K[2][64][128B] | Vt[2][64][128B] | P[128][128B]  (XOR-swizzled rows)
// ---------------------------------------------------------------------------
#define KVB   8192                         // 64 rows * 128 B
#define SM_PB (4 * KVB)                    // P base byte offset = 32768
#define ATT_SMEM (SM_PB + 128 * 128)       // 49152 bytes

__global__ __launch_bounds__(256, 2)
void attn_f16()
{
    extern __shared__ char smc[];
    __half* Psh = (__half*)(smc + SM_PB);

    const int tid  = threadIdx.x;
    const int lane = tid & 31;
    const int w    = tid >> 5;
    const int g    = lane >> 2;
    const int t    = lane & 3;
    const int r8   = lane & 7;
    const int sel  = lane >> 3;
    const int bh   = blockIdx.y;
    const int t0   = blockIdx.x << 7;

    const __half* Kg  = g_k  + (size_t)bh * SEQ * HD;
    const __half* Vtg = g_vt + (size_t)bh * HD * SEQ;

    const unsigned sbase = (unsigned)__cvta_generic_to_shared(smc);

    // ldmatrix lane row bases (byte offsets)
    const unsigned kRow = (unsigned)((((sel >> 1) << 3) + r8) * 128);   // B-frag rows
    const unsigned pRow = (unsigned)((w * 16 + ((sel & 1) << 3) + r8) * 128); // A-frag rows
    const int bc = sel & 1;     // B chunk half
    const int ac = sel >> 1;    // A chunk half

    const int rmin = t0 + w * 16;
    const int r0 = rmin + g;
    const int r1 = r0 + 8;

    // Q fragments in registers: 4 k16 groups x 4 regs.
    unsigned qa[4][4];
    {
        const __half* q0 = g_q + (size_t)bh * SEQ * HD + (size_t)r0 * HD;
        #pragma unroll
        for (int kg = 0; kg < 4; ++kg) {
            qa[kg][0] = *(const unsigned*)(q0 + kg * 16 + 2 * t);
            qa[kg][1] = *(const unsigned*)(q0 + 512 + kg * 16 + 2 * t);   // +8 rows
            qa[kg][2] = *(const unsigned*)(q0 + kg * 16 + 2 * t + 8);
            qa[kg][3] = *(const unsigned*)(q0 + 512 + kg * 16 + 2 * t + 8);
        }
    }

    // Stage K tile (rows=key) and Vt tile (rows=d): 512 chunks each -> 2/thread
    #define ASTAGE(kbase, s)                                                     \
        do {                                                                     \
            _Pragma("unroll")                                                    \
            for (int it2 = 0; it2 < 2; ++it2) {                                  \
                int idx = tid + (it2 << 8);                                      \
                int row = idx >> 3;                                              \
                int c   = idx & 7;                                               \
                unsigned off = (unsigned)(row * 128 + ((c ^ (row & 7)) << 4))    \
                             + (unsigned)(s) * KVB;                              \
                cp_async16(sbase + off,            Kg  + (size_t)((kbase) + row) * 64 + c * 8); \
                cp_async16(sbase + off + 2 * KVB,  Vtg + (size_t)row * SEQ + (kbase) + c * 8);  \
            }                                                                    \
            cp_commit();                                                         \
        } while (0)

    float oa[8][4];
    #pragma unroll
    for (int j = 0; j < 8; ++j)
        #pragma unroll
        for (int r = 0; r < 4; ++r) oa[j][r] = 0.0f;
    float m0 = -1e30f, m1 = -1e30f, l0 = 0.0f, l1 = 0.0f;

    int lo = t0 - (WINDOW - 1); if (lo < 0) lo = 0;
    const int lo_tile = lo >> 6;
    const int hi_tile = (t0 + 127) >> 6;
    const int extra   = (lo_tile > 0) ? 1 : 0;
    const int ntiles  = hi_tile - lo_tile + 1 + extra;

    #define KBASE(i) ((extra ? (((i) == 0) ? 0 : (lo_tile + (i) - 1)) : (lo_tile + (i))) << 6)

    ASTAGE(KBASE(0), 0);

    int buf = 0;
    for (int it = 0; it < ntiles; ++it) {
        const int kbase = KBASE(it);
        cp_wait<0>();
        __syncthreads();
        if (it + 1 < ntiles) ASTAGE(KBASE(it + 1), buf ^ 1);

        const unsigned kT = sbase + (unsigned)buf * KVB;
        const unsigned vT = kT + 2 * KVB;

        // S = Q K^T : 16 x 64 per warp
        float sc[8][4];
        #pragma unroll
        for (int j = 0; j < 8; ++j)
            #pragma unroll
            for (int r = 0; r < 4; ++r) sc[j][r] = 0.0f;

        #pragma unroll
        for (int kg = 0; kg < 4; ++kg) {
            const unsigned bxc = (unsigned)(((2 * kg + bc) ^ r8) << 4);
            #pragma unroll
            for (int p = 0; p < 4; ++p) {
                unsigned b0[2], b1[2];
                ldsm4(b0[0], b0[1], b1[0], b1[1],
                      kT + kRow + (unsigned)(p * 2048) + bxc);
                mma_f16(sc[2 * p],     qa[kg], b0);
                mma_f16(sc[2 * p + 1], qa[kg], b1);
            }
        }

        // Mask (skipped for fully-unmasked warp tiles) + online softmax
        const bool full = (kbase + 63 <= rmin) && ((rmin + 15 - kbase) < WINDOW);
        if (!full) {
            #pragma unroll
            for (int j = 0; j < 8; ++j) {
                int kc0 = kbase + j * 8 + (t << 1);
                int kc1 = kc0 + 1;
                bool a00 = (kc0 <= r0) && ((kc0 < PREFIX) || ((r0 - kc0) < WINDOW));
                bool a01 = (kc1 <= r0) && ((kc1 < PREFIX) || ((r0 - kc1) < WINDOW));
                bool a10 = (kc0 <= r1) && ((kc0 < PREFIX) || ((r1 - kc0) < WINDOW));
                bool a11 = (kc1 <= r1) && ((kc1 < PREFIX) || ((r1 - kc1) < WINDOW));
                if (!a00) sc[j][0] = -1e30f;
                if (!a01) sc[j][1] = -1e30f;
                if (!a10) sc[j][2] = -1e30f;
                if (!a11) sc[j][3] = -1e30f;
            }
        }
        float rmax0 = -1e30f, rmax1 = -1e30f;
        #pragma unroll
        for (int j = 0; j < 8; ++j) {
            rmax0 = fmaxf(rmax0, fmaxf(sc[j][0], sc[j][1]));
            rmax1 = fmaxf(rmax1, fmaxf(sc[j][2], sc[j][3]));
        }
        rmax0 = fmaxf(rmax0, __shfl_xor_sync(0xffffffffu, rmax0, 1));
        rmax0 = fmaxf(rmax0, __shfl_xor_sync(0xffffffffu, rmax0, 2));
        rmax1 = fmaxf(rmax1, __shfl_xor_sync(0xffffffffu, rmax1, 1));
        rmax1 = fmaxf(rmax1, __shfl_xor_sync(0xffffffffu, rmax1, 2));

        float mn0 = fmaxf(fmaxf(m0, rmax0), -1e28f);
        float mn1 = fmaxf(fmaxf(m1, rmax1), -1e28f);
        float esc0 = __expf(m0 - mn0);
        float esc1 = __expf(m1 - mn1);

        float rs0 = 0.0f, rs1 = 0.0f;
        #pragma unroll
        for (int j = 0; j < 8; ++j) {
            float p0 = __expf(sc[j][0] - mn0);
            float p1 = __expf(sc[j][1] - mn0);
            float p2 = __expf(sc[j][2] - mn1);
            float p3 = __expf(sc[j][3] - mn1);
            rs0 += p0 + p1;
            rs1 += p2 + p3;
            // P store (fp16, swizzled 128B rows): row g and row g+8
            int row0 = w * 16 + g;
            unsigned i0 = (unsigned)(row0 * 64 + ((j ^ g) << 3) + 2 * t);
            *(__half2*)(Psh + i0)           = __floats2half2_rn(p0, p1);
            *(__half2*)(Psh + i0 + 8 * 64)  = __floats2half2_rn(p2, p3);
        }
        rs0 += __shfl_xor_sync(0xffffffffu, rs0, 1);
        rs0 += __shfl_xor_sync(0xffffffffu, rs0, 2);
        rs1 += __shfl_xor_sync(0xffffffffu, rs1, 1);
        rs1 += __shfl_xor_sync(0xffffffffu, rs1, 2);

        l0 = l0 * esc0 + rs0;
        l1 = l1 * esc1 + rs1;
        m0 = mn0;
        m1 = mn1;
        #pragma unroll
        for (int j = 0; j < 8; ++j) {
            oa[j][0] *= esc0; oa[j][1] *= esc0;
            oa[j][2] *= esc1; oa[j][3] *= esc1;
        }
        __syncwarp();                           // P rows are warp-private

        // O += P V : 16 x 64 per warp
        #pragma unroll
        for (int kg = 0; kg < 4; ++kg) {
            unsigned pa[4];
            const unsigned axc = (unsigned)(((2 * kg + ac) ^ r8) << 4);
            ldsm4(pa[0], pa[1], pa[2], pa[3],
                  sbase + SM_PB + pRow + axc);
            const unsigned bxc = (unsigned)(((2 * kg + bc) ^ r8) << 4);
            #pragma unroll
            for (int p = 0; p < 4; ++p) {
                unsigned b0[2], b1[2];
                ldsm4(b0[0], b0[1], b1[0], b1[1],
                      vT + kRow + (unsigned)(p * 2048) + bxc);
                mma_f16(oa[2 * p],     pa, b0);
                mma_f16(oa[2 * p + 1], pa, b1);
            }
        }
        buf ^= 1;
    }

    // Finalize: g_o[b][s][h*64+d] (fp16 for the out-proj GEMM)
    const int b = bh >> 4, h = bh & 15;
    const float inv0 = 1.0f / l0;
    const float inv1 = 1.0f / l1;
    __half* d0 = g_o + ((size_t)b * SEQ + r0) * DM + h * HD;
    __half* d1 = g_o + ((size_t)b * SEQ + r1) * DM + h * HD;
    #pragma unroll
    for (int j = 0; j < 8; ++j) {
        int col = j * 8 + (t << 1);
        *(__half2*)(d0 + col) = __floats2half2_rn(oa[j][0] * inv0, oa[j][1] * inv0);
        *(__half2*)(d1 + col) = __floats2half2_rn(oa[j][2] * inv1, oa[j][3] * inv1);
    }
    #undef ASTAGE
    #undef KBASE
}

// ---------------------------------------------------------------------------
extern "C" void kernel_launch(void* const* d_in, const int* in_sizes, int n_in,
                              void* d_out, int out_size)
{
    const float* x     = (const float*)d_in[0];
    const float* w_qkv = (const float*)d_in[1];
    const float* w_out = (const float*)d_in[2];
    float* out = (float*)d_out;

    cudaFuncSetAttribute(gemm_f16<true>,  cudaFuncAttributeMaxDynamicSharedMemorySize, GEMM_SMEM);
    cudaFuncSetAttribute(gemm_f16<false>, cudaFuncAttributeMaxDynamicSharedMemorySize, GEMM_SMEM);
    cudaFuncSetAttribute(attn_f16,        cudaFuncAttributeMaxDynamicSharedMemorySize, ATT_SMEM);

    // 0) fp16-convert all GEMM inputs once
    prep_f16<<<(unsigned)((NX + NW1 + NW2) / 4 / 256), 256>>>(x, w_qkv, w_out);
    // 1) QKV projection -> g_q/g_k/g_vt (v transposed), fp16
    gemm_f16<true><<<dim3(3072 / 128, 8192 / 128), 256, GEMM_SMEM>>>(nullptr);
    // 2) fp16 tensor-core flash attention -> g_o
    attn_f16<<<dim3(SEQ / 128, BATCH * NH), 256, ATT_SMEM>>>();
    // 3) output projection -> d_out (f32)
    gemm_f16<false><<<dim3(1024 / 128, 8192 / 128), 256, GEMM_SMEM>>>(out);
}